// round 16
// baseline (speedup 1.0000x reference)
#include <cuda_runtime.h>
#include <cuda_fp16.h>
#include <cstdint>

#define B_   4
#define H_   16
#define T_   2048
#define C_   1024
#define D_   64
#define BH_  64

__device__ __half g_qh [BH_*T_*D_];
__device__ __half g_kh [BH_*T_*D_];
__device__ __half g_vh [BH_*T_*D_];
__device__ __half g_att[BH_*T_*D_];
__device__ float  g_invZ[BH_*T_];
__device__ __half g_xh [B_*T_*C_];
__device__ __half g_wh [3*H_*C_*D_];     // [z][h][c][d]
__device__ __half g_woh[C_*C_];          // [c][n]

// ================= helpers =================
__device__ __forceinline__ void mma16(float4 &c, const uint32_t* a, const uint32_t* b){
    asm volatile("mma.sync.aligned.m16n8k16.row.col.f32.f16.f16.f32 "
        "{%0,%1,%2,%3}, {%4,%5,%6,%7}, {%8,%9}, {%0,%1,%2,%3};"
        : "+f"(c.x), "+f"(c.y), "+f"(c.z), "+f"(c.w)
        : "r"(a[0]), "r"(a[1]), "r"(a[2]), "r"(a[3]), "r"(b[0]), "r"(b[1]));
}
__device__ __forceinline__ void ldmA(uint32_t* r, uint32_t addr){
    asm volatile("ldmatrix.sync.aligned.m8n8.x4.shared.b16 {%0,%1,%2,%3}, [%4];"
        : "=r"(r[0]), "=r"(r[1]), "=r"(r[2]), "=r"(r[3]) : "r"(addr));
}
__device__ __forceinline__ void ldmB(uint32_t* r, uint32_t addr){
    asm volatile("ldmatrix.sync.aligned.m8n8.x2.shared.b16 {%0,%1}, [%2];"
        : "=r"(r[0]), "=r"(r[1]) : "r"(addr));
}
__device__ __forceinline__ void ldmBT(uint32_t* r, uint32_t addr){
    asm volatile("ldmatrix.sync.aligned.m8n8.x2.trans.shared.b16 {%0,%1}, [%2];"
        : "=r"(r[0]), "=r"(r[1]) : "r"(addr));
}
__device__ __forceinline__ void cpa16(uint32_t dst, const void* src){
    asm volatile("cp.async.cg.shared.global [%0], [%1], 16;" :: "r"(dst), "l"(src));
}
#define CP_COMMIT() asm volatile("cp.async.commit_group;" ::: "memory")
#define CP_WAIT0()  asm volatile("cp.async.wait_group 0;"  ::: "memory")
#define CP_WAIT1()  asm volatile("cp.async.wait_group 1;"  ::: "memory")
__device__ __forceinline__ uint32_t h2u(float a, float b){
    __half2 h = __floats2half2_rn(a, b);
    return *(uint32_t*)&h;
}

// lane addressing (units: halves)
#define ROWA(l) (((l)&7) + (((l)>>3)&1)*8)
#define KOFA(l) (((l)>>4)*8)
#define ROWB(l) ((l)&7)
#define KOFB(l) ((((l)>>3)&1)*8)
#define ROWT(l) (((l)&7) + (((l)>>3)&1)*8)

// ================= prep =================
__global__ __launch_bounds__(256) void cvt_kernel(const float* __restrict__ src, __half* __restrict__ dst){
    int i0 = (blockIdx.x*256 + threadIdx.x)*8;
    #pragma unroll
    for(int j=0;j<2;j++){
        float4 v = *(const float4*)(src + i0 + j*4);
        __half2 h0=__floats2half2_rn(v.x,v.y), h1=__floats2half2_rn(v.z,v.w);
        uint2 u; u.x=*(uint32_t*)&h0; u.y=*(uint32_t*)&h1;
        *(uint2*)(dst + i0 + j*4) = u;
    }
}

// =====================================================================
// K1: fused QKV (R15-passing, unchanged).
// =====================================================================
__global__ __launch_bounds__(256) void qkv_kernel()
{
    __shared__ __half As[2][128*40];
    __shared__ __half Bs[2][3*32*72];
    int tid=threadIdx.x, lane=tid&31, w=tid>>5;
    int g=lane>>2, tg=lane&3;
    int wm=w&1, wn=w>>1;
    int bh=blockIdx.y, b=bh>>4, h=bh&15;
    int m0=blockIdx.x*128;
    const __half* xb = g_xh + ((size_t)b*T_+m0)*C_;
    __half* outz[3] = { g_qh + ((size_t)bh*T_+m0)*D_,
                        g_kh + ((size_t)bh*T_+m0)*D_,
                        g_vh + ((size_t)bh*T_+m0)*D_ };

    uint32_t asb[2]={(uint32_t)__cvta_generic_to_shared(As[0]),
                     (uint32_t)__cvta_generic_to_shared(As[1])};
    uint32_t bsb[2]={(uint32_t)__cvta_generic_to_shared(Bs[0]),
                     (uint32_t)__cvta_generic_to_shared(Bs[1])};

    int zj[6], nlj[6];
    #pragma unroll
    for(int j=0;j<6;j++){ int n=wn*48+j*8; zj[j]=n>>6; nlj[j]=n&63; }

    float4 c[4][6];
    #pragma unroll
    for(int i=0;i<4;i++)
        #pragma unroll
        for(int j=0;j<6;j++) c[i][j]=make_float4(0.f,0.f,0.f,0.f);

    const int NC = C_/32;
    {
        #pragma unroll
        for(int i=0;i<2;i++){
            int u=tid+i*256, r=u>>2, un=u&3;
            cpa16(asb[0] + (r*40+un*8)*2, xb + (size_t)r*C_ + un*8);
        }
        #pragma unroll
        for(int i=0;i<3;i++){
            int u=tid+i*256, z=u>>8, rem=u&255, r=rem>>3, un=rem&7;
            cpa16(bsb[0] + z*4608 + (r*72+un*8)*2,
                  g_wh + (((size_t)z*H_+h)*C_ + r)*D_ + un*8);
        }
        CP_COMMIT();
    }

    for(int ch=0; ch<NC; ch++){
        int p=ch&1;
        __syncthreads();
        if(ch+1<NC){
            int k1=(ch+1)*32;
            #pragma unroll
            for(int i=0;i<2;i++){
                int u=tid+i*256, r=u>>2, un=u&3;
                cpa16(asb[p^1] + (r*40+un*8)*2, xb + (size_t)r*C_ + k1 + un*8);
            }
            #pragma unroll
            for(int i=0;i<3;i++){
                int u=tid+i*256, z=u>>8, rem=u&255, r=rem>>3, un=rem&7;
                cpa16(bsb[p^1] + z*4608 + (r*72+un*8)*2,
                      g_wh + (((size_t)z*H_+h)*C_ + k1 + r)*D_ + un*8);
            }
            CP_COMMIT();
            CP_WAIT1();
        } else {
            CP_WAIT0();
        }
        __syncthreads();

        uint32_t aoff = asb[p] + (ROWA(lane)*40 + KOFA(lane))*2;
        uint32_t btof = bsb[p] + (ROWT(lane)*72)*2;
        #pragma unroll
        for(int ks=0;ks<2;ks++){
            uint32_t a[4][4], bb[6][2];
            #pragma unroll
            for(int i=0;i<4;i++) ldmA(a[i], aoff + ((wm*4+i)*16*40 + ks*16)*2);
            #pragma unroll
            for(int j=0;j<6;j++) ldmBT(bb[j], btof + (zj[j]*2304 + ks*16*72 + nlj[j])*2);
            #pragma unroll
            for(int i=0;i<4;i++)
                #pragma unroll
                for(int j=0;j<6;j++) mma16(c[i][j], a[i], bb[j]);
        }
    }
    #pragma unroll
    for(int i=0;i<4;i++){
        int m=wm*64+i*16+g;
        #pragma unroll
        for(int j=0;j<6;j++){
            int d=nlj[j]+2*tg;
            __half* oz=outz[zj[j]];
            *(__half2*)(oz+(size_t)m*D_+d)     = __floats2half2_rn(c[i][j].x, c[i][j].y);
            *(__half2*)(oz+(size_t)(m+8)*D_+d) = __floats2half2_rn(c[i][j].z, c[i][j].w);
        }
    }
}

// =====================================================================
// K2: per-key Z, K-block A-fragments in REGISTERS. Block 128 keys,
// 64-query stream tiles double-buffered. 8 warps (4s x 2t) of 32x32.
// smem 18.5KB -> 2 CTAs/SM possible.
// =====================================================================
__global__ __launch_bounds__(256) void colsum_kernel()
{
    __shared__ __half Qb[2][64*72];
    __shared__ float zsh[128];
    int tid=threadIdx.x, lane=tid&31, w=tid>>5;
    int g=lane>>2, tg=lane&3;
    int wm=w&3, wn=w>>2;
    int bh=blockIdx.y, s0=blockIdx.x*128;
    const __half* kb=g_kh+(size_t)bh*T_*D_;
    const __half* qb=g_qh+(size_t)bh*T_*D_;
    uint32_t qsb[2]={(uint32_t)__cvta_generic_to_shared(Qb[0]),
                     (uint32_t)__cvta_generic_to_shared(Qb[1])};

    if(tid<128) zsh[tid]=0.f;
    // stage K block 128x64 into Qb[0] (rows 0-63) + Qb[1] (rows 64-127)
    #pragma unroll
    for(int i=0;i<4;i++){
        int idx=tid+i*256, r=idx>>3, c8=(idx&7)*8;
        __half* dst = (r<64)? &Qb[0][r*72+c8] : &Qb[1][(r-64)*72+c8];
        *(uint4*)dst = *(const uint4*)(kb+(size_t)(s0+r)*D_+c8);
    }
    __syncthreads();
    // extract this warp's K A-frags (rows wm*32 .. wm*32+31)
    uint32_t aK[2][4][4];
    {
        uint32_t base = qsb[wm>>1];
        int r0=(wm&1)*32;
        #pragma unroll
        for(int mt=0;mt<2;mt++)
            #pragma unroll
            for(int ks=0;ks<4;ks++)
                ldmA(aK[mt][ks], base + ((r0+mt*16+ROWA(lane))*72 + ks*16 + KOFA(lane))*2);
    }
    __syncthreads();
    // prefetch first Q tile
    #pragma unroll
    for(int i=0;i<2;i++){
        int idx=tid+i*256, rr=idx>>3, cc=(idx&7)*8;
        cpa16(qsb[0] + (rr*72+cc)*2, qb+(size_t)(s0+rr)*D_+cc);
    }
    CP_COMMIT();

    float zrow[2][2];
    zrow[0][0]=zrow[0][1]=zrow[1][0]=zrow[1][1]=0.f;

    for(int t0=s0; t0<T_; t0+=64){
        int p=((t0-s0)>>6)&1;
        CP_WAIT0();
        __syncthreads();
        if(t0+64<T_){
            #pragma unroll
            for(int i=0;i<2;i++){
                int idx=tid+i*256, rr=idx>>3, cc=(idx&7)*8;
                cpa16(qsb[p^1] + (rr*72+cc)*2, qb+(size_t)(t0+64+rr)*D_+cc);
            }
            CP_COMMIT();
        }
        uint32_t boff = qsb[p] + (ROWB(lane)*72 + KOFB(lane))*2;

        float4 c[2][4];
        #pragma unroll
        for(int i=0;i<2;i++)
            #pragma unroll
            for(int j=0;j<4;j++) c[i][j]=make_float4(0.f,0.f,0.f,0.f);
        #pragma unroll
        for(int ks=0;ks<4;ks++){
            uint32_t bb[4][2];
            #pragma unroll
            for(int j=0;j<4;j++) ldmB(bb[j], boff + ((wn*4+j)*8*72 + ks*16)*2);
            #pragma unroll
            for(int i=0;i<2;i++)
                #pragma unroll
                for(int j=0;j<4;j++) mma16(c[i][j], aK[i][ks], bb[j]);
        }
        bool full = (t0 - s0) >= 128;
        #pragma unroll
        for(int i=0;i<2;i++){
            int sr0=s0+wm*32+i*16+g, sr1=sr0+8;
            #pragma unroll
            for(int j=0;j<4;j++){
                int tc0=t0+wn*32+j*8+2*tg, tc1=tc0+1;
                float4 S=c[i][j];
                zrow[i][0] += (full||tc0>=sr0)?__expf(S.x*0.125f):0.f;
                zrow[i][0] += (full||tc1>=sr0)?__expf(S.y*0.125f):0.f;
                zrow[i][1] += (full||tc0>=sr1)?__expf(S.z*0.125f):0.f;
                zrow[i][1] += (full||tc1>=sr1)?__expf(S.w*0.125f):0.f;
            }
        }
    }
    __syncthreads();
    #pragma unroll
    for(int i=0;i<2;i++)
        #pragma unroll
        for(int rr=0;rr<2;rr++){
            float v=zrow[i][rr];
            v += __shfl_xor_sync(0xffffffffu, v, 1);
            v += __shfl_xor_sync(0xffffffffu, v, 2);
            if(tg==0) atomicAdd(&zsh[wm*32+i*16+g+rr*8], v);
        }
    __syncthreads();
    if(tid<128) g_invZ[(size_t)bh*T_+s0+tid]=1.0f/zsh[tid];
}

// =====================================================================
// K3: attention v3. Block 128 q; warps = 4 q-groups(32q) x 2 s-halves.
// Q A-frags in registers; 64-key K/V tiles double-buffered; per-warp
// partial O over its s-half; cross-half reduction via smem epilogue.
// smem: one 36.9KB arena (Kb0,Kb1,Vb0,Vb1 / reused as fp32 O scratch).
// =====================================================================
__global__ __launch_bounds__(256) void attn_kernel()
{
    __shared__ __align__(1024) __half SM[4*64*72];   // 36864B
    int tid=threadIdx.x, lane=tid&31, w=tid>>5;
    int g=lane>>2, tg=lane&3;
    int qg=w&3, sh=w>>2;
    int bh=blockIdx.y;
    int t0=((int)gridDim.x-1-(int)blockIdx.x)*128;   // big tiles first
    const __half* qb=g_qh+(size_t)bh*T_*D_;
    const __half* kb=g_kh+(size_t)bh*T_*D_;
    const __half* vb=g_vh+(size_t)bh*T_*D_;
    const float* iz=g_invZ+(size_t)bh*T_;

    uint32_t smb=(uint32_t)__cvta_generic_to_shared(SM);
    uint32_t ksb[2]={smb, smb+9216};
    uint32_t vsb[2]={smb+18432, smb+27648};

    // stage Q 128x64 into SM[0..18432): rows 0-63 at 0, 64-127 at 9216
    #pragma unroll
    for(int i=0;i<4;i++){
        int idx=tid+i*256, r=idx>>3, c8=(idx&7)*8;
        __half* dst = SM + ((r<64)? r*72+c8 : 4608 + (r-64)*72+c8);
        *(uint4*)dst = *(const uint4*)(qb+(size_t)(t0+r)*D_+c8);
    }
    __syncthreads();
    // extract Q A-frags for this warp (rows qg*32 .. +31)
    uint32_t aQ[2][4][4];
    {
        uint32_t base = ksb[qg>>1];
        int r0=(qg&1)*32;
        #pragma unroll
        for(int mt=0;mt<2;mt++)
            #pragma unroll
            for(int ks=0;ks<4;ks++)
                ldmA(aQ[mt][ks], base + ((r0+mt*16+ROWA(lane))*72 + ks*16 + KOFA(lane))*2);
    }
    __syncthreads();
    // prefetch first K/V tile (s0=0) into buffers 0
    #pragma unroll
    for(int i=0;i<2;i++){
        int idx=tid+i*256, r=idx>>3, c8=(idx&7)*8;
        cpa16(ksb[0] + (r*72+c8)*2, kb+(size_t)r*D_+c8);
        cpa16(vsb[0] + (r*72+c8)*2, vb+(size_t)r*D_+c8);
    }
    CP_COMMIT();

    float4 oacc[2][8];
    #pragma unroll
    for(int i=0;i<2;i++)
        #pragma unroll
        for(int j=0;j<8;j++) oacc[i][j]=make_float4(0.f,0.f,0.f,0.f);

    int send=t0+64;
    for(int s0=0; s0<=send; s0+=64){
        int p=(s0>>6)&1;
        CP_WAIT0();
        __syncthreads();
        if(s0+64<=send){
            int s1b=s0+64;
            #pragma unroll
            for(int i=0;i<2;i++){
                int idx=tid+i*256, r=idx>>3, c8=(idx&7)*8;
                cpa16(ksb[p^1] + (r*72+c8)*2, kb+(size_t)(s1b+r)*D_+c8);
                cpa16(vsb[p^1] + (r*72+c8)*2, vb+(size_t)(s1b+r)*D_+c8);
            }
            CP_COMMIT();
        }
        uint32_t kBoff = ksb[p] + ((sh*32+ROWB(lane))*72 + KOFB(lane))*2;
        uint32_t vToff = vsb[p] + ((sh*32+ROWT(lane))*72)*2;

        // stage1: S[32q x 32s_half], nA=2(regs) x nB=4
        float4 s1[2][4];
        #pragma unroll
        for(int i=0;i<2;i++)
            #pragma unroll
            for(int j=0;j<4;j++) s1[i][j]=make_float4(0.f,0.f,0.f,0.f);
        #pragma unroll
        for(int ks=0;ks<4;ks++){
            uint32_t bb[4][2];
            #pragma unroll
            for(int j=0;j<4;j++) ldmB(bb[j], kBoff + (j*8*72 + ks*16)*2);
            #pragma unroll
            for(int i=0;i<2;i++)
                #pragma unroll
                for(int j=0;j<4;j++) mma16(s1[i][j], aQ[i][ks], bb[j]);
        }
        // exp * invZ (in place), masked only on the last two tiles
        bool msk=(s0>=t0);
        #pragma unroll
        for(int i=0;i<2;i++){
            int qg0=t0+qg*32+i*16+g, qg1=qg0+8;
            #pragma unroll
            for(int j=0;j<4;j++){
                int sg0=s0+sh*32+j*8+2*tg, sg1=sg0+1;
                float iz0=__ldg(iz+sg0), iz1=__ldg(iz+sg1);
                float4 S=s1[i][j];
                s1[i][j].x=(!msk||qg0>=sg0)?__expf(S.x*0.125f)*iz0:0.f;
                s1[i][j].y=(!msk||qg0>=sg1)?__expf(S.y*0.125f)*iz1:0.f;
                s1[i][j].z=(!msk||qg1>=sg0)?__expf(S.z*0.125f)*iz0:0.f;
                s1[i][j].w=(!msk||qg1>=sg1)?__expf(S.w*0.125f)*iz1:0.f;
            }
        }
        // pack P C-frags -> A-frags (k = 32 s_half = 2 k16)
        uint32_t aP[2][2][4];
        #pragma unroll
        for(int i=0;i<2;i++)
            #pragma unroll
            for(int k2=0;k2<2;k2++){
                aP[i][k2][0]=h2u(s1[i][2*k2].x,   s1[i][2*k2].y);
                aP[i][k2][1]=h2u(s1[i][2*k2].z,   s1[i][2*k2].w);
                aP[i][k2][2]=h2u(s1[i][2*k2+1].x, s1[i][2*k2+1].y);
                aP[i][k2][3]=h2u(s1[i][2*k2+1].z, s1[i][2*k2+1].w);
            }
        // stage2: O_partial[32q x 64d] += P(32x32).V(32x64), nA=2 x nB=8
        #pragma unroll
        for(int k2=0;k2<2;k2++){
            uint32_t bbv[8][2];
            #pragma unroll
            for(int nt=0;nt<8;nt++) ldmBT(bbv[nt], vToff + (k2*16*72 + nt*8)*2);
            #pragma unroll
            for(int i=0;i<2;i++)
                #pragma unroll
                for(int nt=0;nt<8;nt++) mma16(oacc[i][nt], aP[i][k2], bbv[nt]);
        }
    }

    // cross-half reduction: sh==1 stores fp32 partials, sh==0 adds + writes
    __syncthreads();
    float* red = (float*)SM;      // 128 x 68 fp32 = 34816B <= 36864B
    if(sh==1){
        #pragma unroll
        for(int i=0;i<2;i++){
            int q=qg*32+i*16+g;
            #pragma unroll
            for(int nt=0;nt<8;nt++){
                int d=nt*8+2*tg;
                *(float2*)&red[q*68+d]     = make_float2(oacc[i][nt].x, oacc[i][nt].y);
                *(float2*)&red[(q+8)*68+d] = make_float2(oacc[i][nt].z, oacc[i][nt].w);
            }
        }
    }
    __syncthreads();
    if(sh==0){
        __half* ob=g_att+((size_t)bh*T_+t0)*D_;
        #pragma unroll
        for(int i=0;i<2;i++){
            int q=qg*32+i*16+g;
            #pragma unroll
            for(int nt=0;nt<8;nt++){
                int d=nt*8+2*tg;
                float2 r0=*(float2*)&red[q*68+d];
                float2 r1=*(float2*)&red[(q+8)*68+d];
                *(__half2*)(ob+(size_t)q*D_+d)     = __floats2half2_rn(oacc[i][nt].x+r0.x, oacc[i][nt].y+r0.y);
                *(__half2*)(ob+(size_t)(q+8)*D_+d) = __floats2half2_rn(oacc[i][nt].z+r1.x, oacc[i][nt].w+r1.y);
            }
        }
    }
}

// =====================================================================
// K4: output projection + bias (R15-passing, unchanged).
// =====================================================================
__global__ __launch_bounds__(256) void oproj_kernel(
    const float* __restrict__ bo, float* __restrict__ out)
{
    __shared__ __half As[2][128*40];
    __shared__ __half Bs[2][32*136];
    int tid=threadIdx.x, lane=tid&31, w=tid>>5;
    int g=lane>>2, tg=lane&3;
    int wm=w&1, wn=w>>1;
    int m0=blockIdx.x*128, n0=blockIdx.y*128;

    uint32_t asb[2]={(uint32_t)__cvta_generic_to_shared(As[0]),
                     (uint32_t)__cvta_generic_to_shared(As[1])};
    uint32_t bsb[2]={(uint32_t)__cvta_generic_to_shared(Bs[0]),
                     (uint32_t)__cvta_generic_to_shared(Bs[1])};

    float4 c[4][4];
    #pragma unroll
    for(int i=0;i<4;i++)
        #pragma unroll
        for(int j=0;j<4;j++) c[i][j]=make_float4(0.f,0.f,0.f,0.f);

    const int NC = C_/32;
    auto prefetch = [&](int ch, int p){
        int k0=ch*32, hk=k0>>6, dk=k0&32 ? 32 : 0;
        #pragma unroll
        for(int i=0;i<2;i++){
            int u=tid+i*256, r=u>>2, un=u&3;
            int mg=m0+r, b=mg>>11, t=mg&2047;
            cpa16(asb[p] + (r*40+un*8)*2,
                  g_att + (((size_t)(b*H_+hk))*T_+t)*D_ + dk + un*8);
        }
        #pragma unroll
        for(int i=0;i<2;i++){
            int u=tid+i*256, r=u>>4, un=u&15;
            cpa16(bsb[p] + (r*136+un*8)*2,
                  g_woh + (size_t)(k0+r)*C_ + n0 + un*8);
        }
        CP_COMMIT();
    };

    prefetch(0, 0);
    for(int ch=0; ch<NC; ch++){
        int p=ch&1;
        __syncthreads();
        if(ch+1<NC){ prefetch(ch+1, p^1); CP_WAIT1(); }
        else       { CP_WAIT0(); }
        __syncthreads();

        uint32_t aoff = asb[p] + (ROWA(lane)*40 + KOFA(lane))*2;
        uint32_t btof = bsb[p] + (ROWT(lane)*136)*2;
        #pragma unroll
        for(int ks=0;ks<2;ks++){
            uint32_t a[4][4], bb[4][2];
            #pragma unroll
            for(int i=0;i<4;i++) ldmA(a[i], aoff + ((wm*4+i)*16*40 + ks*16)*2);
            #pragma unroll
            for(int j=0;j<4;j++) ldmBT(bb[j], btof + (ks*16*136 + (wn*4+j)*8)*2);
            #pragma unroll
            for(int i=0;i<4;i++)
                #pragma unroll
                for(int j=0;j<4;j++) mma16(c[i][j], a[i], bb[j]);
        }
    }
    #pragma unroll
    for(int i=0;i<4;i++){
        int m=m0+wm*64+i*16+g;
        #pragma unroll
        for(int j=0;j<4;j++){
            int n=n0+wn*32+j*8+2*tg;
            float b0v=bo[n], b1v=bo[n+1];
            *(float2*)(out+(size_t)m*C_+n)     = make_float2(c[i][j].x+b0v, c[i][j].y+b1v);
            *(float2*)(out+(size_t)(m+8)*C_+n) = make_float2(c[i][j].z+b0v, c[i][j].w+b1v);
        }
    }
}

// =====================================================================
extern "C" void kernel_launch(void* const* d_in, const int* in_sizes, int n_in,
                              void* d_out, int out_size)
{
    const float* x  = (const float*)d_in[0];
    const float* Wq = (const float*)d_in[1];
    const float* Wk = (const float*)d_in[2];
    const float* Wv = (const float*)d_in[3];
    const float* Wo = (const float*)d_in[4];
    const float* bo = (const float*)d_in[5];
    float* out = (float*)d_out;

    __half *xh, *wh, *woh;
    cudaGetSymbolAddress((void**)&xh,  g_xh);
    cudaGetSymbolAddress((void**)&wh,  g_wh);
    cudaGetSymbolAddress((void**)&woh, g_woh);

    cvt_kernel<<<B_*T_*C_/2048, 256>>>(x,  xh);
    cvt_kernel<<<H_*C_*D_/2048, 256>>>(Wq, wh);
    cvt_kernel<<<H_*C_*D_/2048, 256>>>(Wk, wh +   (size_t)H_*C_*D_);
    cvt_kernel<<<H_*C_*D_/2048, 256>>>(Wv, wh + 2*(size_t)H_*C_*D_);
    cvt_kernel<<<C_*C_/2048,    256>>>(Wo, woh);

    qkv_kernel   <<<dim3(T_/128, BH_), 256>>>();
    colsum_kernel<<<dim3(T_/128, BH_), 256>>>();
    attn_kernel  <<<dim3(T_/128, BH_), 256>>>();
    oproj_kernel <<<dim3((B_*T_)/128, C_/128), 256>>>(bo, out);
}

// round 17
// speedup vs baseline: 1.1369x; 1.1369x over previous
#include <cuda_runtime.h>
#include <cuda_fp16.h>
#include <cstdint>

#define B_   4
#define H_   16
#define T_   2048
#define C_   1024
#define D_   64
#define BH_  64

__device__ __half g_qh [BH_*T_*D_];
__device__ __half g_kh [BH_*T_*D_];
__device__ __half g_vh [BH_*T_*D_];
__device__ __half g_att[BH_*T_*D_];
__device__ float  g_invZ[BH_*T_];
__device__ __half g_xh [B_*T_*C_];       // x fp16
__device__ __half g_wh [3*H_*C_*D_];     // Wq/Wk/Wv fp16, layout [z][h][c][d]
__device__ __half g_woh[C_*C_];          // Wo fp16, layout [c][n]

// ================= helpers =================
__device__ __forceinline__ void mma16(float4 &c, const uint32_t* a, const uint32_t* b){
    asm volatile("mma.sync.aligned.m16n8k16.row.col.f32.f16.f16.f32 "
        "{%0,%1,%2,%3}, {%4,%5,%6,%7}, {%8,%9}, {%0,%1,%2,%3};"
        : "+f"(c.x), "+f"(c.y), "+f"(c.z), "+f"(c.w)
        : "r"(a[0]), "r"(a[1]), "r"(a[2]), "r"(a[3]), "r"(b[0]), "r"(b[1]));
}
__device__ __forceinline__ void ldmA(uint32_t* r, uint32_t addr){
    asm volatile("ldmatrix.sync.aligned.m8n8.x4.shared.b16 {%0,%1,%2,%3}, [%4];"
        : "=r"(r[0]), "=r"(r[1]), "=r"(r[2]), "=r"(r[3]) : "r"(addr));
}
__device__ __forceinline__ void ldmB(uint32_t* r, uint32_t addr){
    asm volatile("ldmatrix.sync.aligned.m8n8.x2.shared.b16 {%0,%1}, [%2];"
        : "=r"(r[0]), "=r"(r[1]) : "r"(addr));
}
__device__ __forceinline__ void ldmBT(uint32_t* r, uint32_t addr){
    asm volatile("ldmatrix.sync.aligned.m8n8.x2.trans.shared.b16 {%0,%1}, [%2];"
        : "=r"(r[0]), "=r"(r[1]) : "r"(addr));
}
__device__ __forceinline__ void cpa16(uint32_t dst, const void* src){
    asm volatile("cp.async.cg.shared.global [%0], [%1], 16;" :: "r"(dst), "l"(src));
}
#define CP_COMMIT() asm volatile("cp.async.commit_group;" ::: "memory")
#define CP_WAIT0()  asm volatile("cp.async.wait_group 0;"  ::: "memory")
#define CP_WAIT1()  asm volatile("cp.async.wait_group 1;"  ::: "memory")
__device__ __forceinline__ uint32_t h2u(float a, float b){
    __half2 h = __floats2half2_rn(a, b);
    return *(uint32_t*)&h;
}

// lane addressing (units: halves)
#define ROWA(l) (((l)&7) + (((l)>>3)&1)*8)
#define KOFA(l) (((l)>>4)*8)
#define ROWB(l) ((l)&7)
#define KOFB(l) ((((l)>>3)&1)*8)
#define ROWT(l) (((l)&7) + (((l)>>3)&1)*8)

// ================= prep: single merged fp32->fp16 convert =================
// block ranges: [0,4096) x | [4096,4608) Wq | [4608,5120) Wk | [5120,5632) Wv | [5632,6144) Wo
__global__ __launch_bounds__(256) void cvt_all_kernel(
    const float* __restrict__ x,  const float* __restrict__ Wq,
    const float* __restrict__ Wk, const float* __restrict__ Wv,
    const float* __restrict__ Wo)
{
    int blk = blockIdx.x;
    const float* src; __half* dst; int base;
    if(blk < 4096){        src=x;  dst=g_xh;                         base=blk; }
    else if(blk < 4608){   src=Wq; dst=g_wh;                         base=blk-4096; }
    else if(blk < 5120){   src=Wk; dst=g_wh +   (size_t)H_*C_*D_;    base=blk-4608; }
    else if(blk < 5632){   src=Wv; dst=g_wh + 2*(size_t)H_*C_*D_;    base=blk-5120; }
    else {                 src=Wo; dst=g_woh;                        base=blk-5632; }
    int i0 = (base*256 + threadIdx.x)*8;
    #pragma unroll
    for(int j=0;j<2;j++){
        float4 v = *(const float4*)(src + i0 + j*4);
        __half2 h0=__floats2half2_rn(v.x,v.y), h1=__floats2half2_rn(v.z,v.w);
        uint2 u; u.x=*(uint32_t*)&h0; u.y=*(uint32_t*)&h1;
        *(uint2*)(dst + i0 + j*4) = u;
    }
}

// =====================================================================
// K1: fused QKV (R15-passing, unchanged).
// =====================================================================
__global__ __launch_bounds__(256) void qkv_kernel()
{
    __shared__ __half As[2][128*40];
    __shared__ __half Bs[2][3*32*72];
    int tid=threadIdx.x, lane=tid&31, w=tid>>5;
    int g=lane>>2, tg=lane&3;
    int wm=w&1, wn=w>>1;
    int bh=blockIdx.y, b=bh>>4, h=bh&15;
    int m0=blockIdx.x*128;
    const __half* xb = g_xh + ((size_t)b*T_+m0)*C_;
    __half* outz[3] = { g_qh + ((size_t)bh*T_+m0)*D_,
                        g_kh + ((size_t)bh*T_+m0)*D_,
                        g_vh + ((size_t)bh*T_+m0)*D_ };

    uint32_t asb[2]={(uint32_t)__cvta_generic_to_shared(As[0]),
                     (uint32_t)__cvta_generic_to_shared(As[1])};
    uint32_t bsb[2]={(uint32_t)__cvta_generic_to_shared(Bs[0]),
                     (uint32_t)__cvta_generic_to_shared(Bs[1])};

    int zj[6], nlj[6];
    #pragma unroll
    for(int j=0;j<6;j++){ int n=wn*48+j*8; zj[j]=n>>6; nlj[j]=n&63; }

    float4 c[4][6];
    #pragma unroll
    for(int i=0;i<4;i++)
        #pragma unroll
        for(int j=0;j<6;j++) c[i][j]=make_float4(0.f,0.f,0.f,0.f);

    const int NC = C_/32;
    {
        #pragma unroll
        for(int i=0;i<2;i++){
            int u=tid+i*256, r=u>>2, un=u&3;
            cpa16(asb[0] + (r*40+un*8)*2, xb + (size_t)r*C_ + un*8);
        }
        #pragma unroll
        for(int i=0;i<3;i++){
            int u=tid+i*256, z=u>>8, rem=u&255, r=rem>>3, un=rem&7;
            cpa16(bsb[0] + z*4608 + (r*72+un*8)*2,
                  g_wh + (((size_t)z*H_+h)*C_ + r)*D_ + un*8);
        }
        CP_COMMIT();
    }

    for(int ch=0; ch<NC; ch++){
        int p=ch&1;
        __syncthreads();
        if(ch+1<NC){
            int k1=(ch+1)*32;
            #pragma unroll
            for(int i=0;i<2;i++){
                int u=tid+i*256, r=u>>2, un=u&3;
                cpa16(asb[p^1] + (r*40+un*8)*2, xb + (size_t)r*C_ + k1 + un*8);
            }
            #pragma unroll
            for(int i=0;i<3;i++){
                int u=tid+i*256, z=u>>8, rem=u&255, r=rem>>3, un=rem&7;
                cpa16(bsb[p^1] + z*4608 + (r*72+un*8)*2,
                      g_wh + (((size_t)z*H_+h)*C_ + k1 + r)*D_ + un*8);
            }
            CP_COMMIT();
            CP_WAIT1();
        } else {
            CP_WAIT0();
        }
        __syncthreads();

        uint32_t aoff = asb[p] + (ROWA(lane)*40 + KOFA(lane))*2;
        uint32_t btof = bsb[p] + (ROWT(lane)*72)*2;
        #pragma unroll
        for(int ks=0;ks<2;ks++){
            uint32_t a[4][4], bb[6][2];
            #pragma unroll
            for(int i=0;i<4;i++) ldmA(a[i], aoff + ((wm*4+i)*16*40 + ks*16)*2);
            #pragma unroll
            for(int j=0;j<6;j++) ldmBT(bb[j], btof + (zj[j]*2304 + ks*16*72 + nlj[j])*2);
            #pragma unroll
            for(int i=0;i<4;i++)
                #pragma unroll
                for(int j=0;j<6;j++) mma16(c[i][j], a[i], bb[j]);
        }
    }
    #pragma unroll
    for(int i=0;i<4;i++){
        int m=wm*64+i*16+g;
        #pragma unroll
        for(int j=0;j<6;j++){
            int d=nlj[j]+2*tg;
            __half* oz=outz[zj[j]];
            *(__half2*)(oz+(size_t)m*D_+d)     = __floats2half2_rn(c[i][j].x, c[i][j].y);
            *(__half2*)(oz+(size_t)(m+8)*D_+d) = __floats2half2_rn(c[i][j].z, c[i][j].w);
        }
    }
}

// =====================================================================
// K2: per-key Z via S^T = K.Q^T (R15-passing, unchanged).
// =====================================================================
__global__ __launch_bounds__(256) void colsum_kernel()
{
    __shared__ __half Kf[128*72];
    __shared__ __half Qf[2][64*72];
    __shared__ float zsh[128];
    int tid=threadIdx.x, lane=tid&31, w=tid>>5;
    int g=lane>>2, tg=lane&3;
    int wm=w&3, wn=w>>2;
    int bh=blockIdx.y, s0=blockIdx.x*128;
    const __half* kb=g_kh+(size_t)bh*T_*D_;
    const __half* qb=g_qh+(size_t)bh*T_*D_;

    uint32_t ksb=(uint32_t)__cvta_generic_to_shared(Kf);
    uint32_t qsb[2]={(uint32_t)__cvta_generic_to_shared(Qf[0]),
                     (uint32_t)__cvta_generic_to_shared(Qf[1])};
    uint32_t aoff = ksb + (ROWA(lane)*72 + KOFA(lane))*2;

    if(tid<128) zsh[tid]=0.f;
    #pragma unroll
    for(int i=0;i<4;i++){
        int idx=tid+i*256, r=idx>>3, c8=(idx&7)*8;
        *(uint4*)&Kf[r*72+c8] = *(const uint4*)(kb+(size_t)(s0+r)*D_+c8);
    }
    #pragma unroll
    for(int i=0;i<2;i++){
        int idx=tid+i*256, rr=idx>>3, cc=(idx&7)*8;
        cpa16(qsb[0] + (rr*72+cc)*2, qb+(size_t)(s0+rr)*D_+cc);
    }
    CP_COMMIT();

    float zrow[2][2];
    zrow[0][0]=zrow[0][1]=zrow[1][0]=zrow[1][1]=0.f;

    for(int t0=s0; t0<T_; t0+=64){
        int p=((t0-s0)>>6)&1;
        CP_WAIT0();
        __syncthreads();
        if(t0+64<T_){
            #pragma unroll
            for(int i=0;i<2;i++){
                int idx=tid+i*256, rr=idx>>3, cc=(idx&7)*8;
                cpa16(qsb[p^1] + (rr*72+cc)*2, qb+(size_t)(t0+64+rr)*D_+cc);
            }
        }
        CP_COMMIT();
        uint32_t boff = qsb[p] + (ROWB(lane)*72 + KOFB(lane))*2;

        float4 c[2][4];
        #pragma unroll
        for(int i=0;i<2;i++)
            #pragma unroll
            for(int j=0;j<4;j++) c[i][j]=make_float4(0.f,0.f,0.f,0.f);
        #pragma unroll
        for(int ks=0;ks<4;ks++){
            uint32_t a[2][4], bb[4][2];
            #pragma unroll
            for(int i=0;i<2;i++) ldmA(a[i], aoff + ((wm*2+i)*16*72 + ks*16)*2);
            #pragma unroll
            for(int j=0;j<4;j++) ldmB(bb[j], boff + ((wn*4+j)*8*72 + ks*16)*2);
            #pragma unroll
            for(int i=0;i<2;i++)
                #pragma unroll
                for(int j=0;j<4;j++) mma16(c[i][j], a[i], bb[j]);
        }
        bool full = (t0 - s0) >= 128;
        #pragma unroll
        for(int i=0;i<2;i++){
            int sr0=s0+wm*32+i*16+g, sr1=sr0+8;
            #pragma unroll
            for(int j=0;j<4;j++){
                int tc0=t0+wn*32+j*8+2*tg, tc1=tc0+1;
                float4 S=c[i][j];
                zrow[i][0] += (full||tc0>=sr0)?__expf(S.x*0.125f):0.f;
                zrow[i][0] += (full||tc1>=sr0)?__expf(S.y*0.125f):0.f;
                zrow[i][1] += (full||tc0>=sr1)?__expf(S.z*0.125f):0.f;
                zrow[i][1] += (full||tc1>=sr1)?__expf(S.w*0.125f):0.f;
            }
        }
    }
    __syncthreads();
    #pragma unroll
    for(int i=0;i<2;i++)
        #pragma unroll
        for(int rr=0;rr<2;rr++){
            float v=zrow[i][rr];
            v += __shfl_xor_sync(0xffffffffu, v, 1);
            v += __shfl_xor_sync(0xffffffffu, v, 2);
            if(tg==0) atomicAdd(&zsh[wm*32+i*16+g+rr*8], v);
        }
    __syncthreads();
    if(tid<128) g_invZ[(size_t)bh*T_+s0+tid]=1.0f/zsh[tid];
}

// =====================================================================
// K3: attention, register P forwarding (R15-passing; only change:
// invZ loads hoisted ahead of stage1 MMAs).
// =====================================================================
__global__ __launch_bounds__(256) void attn_kernel()
{
    __shared__ __half Qf[128*72];
    __shared__ __half Kf[2][32*72];
    __shared__ __half Vf[2][32*72];
    int tid=threadIdx.x, lane=tid&31, w=tid>>5;
    int g=lane>>2, tg=lane&3;
    int bh=blockIdx.y;
    int t0=((int)gridDim.x-1-(int)blockIdx.x)*128;   // big tiles first
    const __half* qb=g_qh+(size_t)bh*T_*D_;
    const __half* kb=g_kh+(size_t)bh*T_*D_;
    const __half* vb=g_vh+(size_t)bh*T_*D_;
    const float* iz=g_invZ+(size_t)bh*T_;

    uint32_t qsb=(uint32_t)__cvta_generic_to_shared(Qf);
    uint32_t ksb[2]={(uint32_t)__cvta_generic_to_shared(Kf[0]),
                     (uint32_t)__cvta_generic_to_shared(Kf[1])};
    uint32_t vsb[2]={(uint32_t)__cvta_generic_to_shared(Vf[0]),
                     (uint32_t)__cvta_generic_to_shared(Vf[1])};
    uint32_t qAoff = qsb + ((w*16+ROWA(lane))*72 + KOFA(lane))*2;

    {
        int r=tid>>3, c8=(tid&7)*8;
        cpa16(ksb[0] + (r*72+c8)*2, kb+(size_t)r*D_+c8);
        cpa16(vsb[0] + (r*72+c8)*2, vb+(size_t)r*D_+c8);
    }
    CP_COMMIT();
    #pragma unroll
    for(int i=0;i<4;i++){
        int idx=tid+i*256, r=idx>>3, c8=(idx&7)*8;
        *(uint4*)&Qf[r*72+c8] = *(const uint4*)(qb+(size_t)(t0+r)*D_+c8);
    }

    float4 oacc[8];
    #pragma unroll
    for(int j=0;j<8;j++) oacc[j]=make_float4(0.f,0.f,0.f,0.f);

    int qg0 = t0 + w*16 + g, qg1 = qg0 + 8;
    int send = t0 + 96;
    for(int s0=0; s0<=send; s0+=32){
        int p=(s0>>5)&1;
        CP_WAIT0();
        __syncthreads();
        if(s0+32<=send){
            int r=tid>>3, c8=(tid&7)*8;
            cpa16(ksb[p^1] + (r*72+c8)*2, kb+(size_t)(s0+32+r)*D_+c8);
            cpa16(vsb[p^1] + (r*72+c8)*2, vb+(size_t)(s0+32+r)*D_+c8);
        }
        CP_COMMIT();
        uint32_t kBoff = ksb[p] + (ROWB(lane)*72 + KOFB(lane))*2;
        uint32_t vToff = vsb[p] + (ROWT(lane)*72)*2;

        // hoist invZ loads: issue before the MMA block so they overlap
        float izv[4][2];
        #pragma unroll
        for(int j=0;j<4;j++){
            int sg0=s0+j*8+2*tg;
            izv[j][0]=__ldg(iz+sg0);
            izv[j][1]=__ldg(iz+sg0+1);
        }

        // stage1: S[16q x 32s] per warp (4 n8-tiles), K=64 (4 ks)
        float4 s1[4];
        #pragma unroll
        for(int j=0;j<4;j++) s1[j]=make_float4(0.f,0.f,0.f,0.f);
        #pragma unroll
        for(int ks=0;ks<4;ks++){
            uint32_t a[4], bb[4][2];
            ldmA(a, qAoff + (ks*16)*2);
            #pragma unroll
            for(int j=0;j<4;j++) ldmB(bb[j], kBoff + (j*8*72 + ks*16)*2);
            #pragma unroll
            for(int j=0;j<4;j++) mma16(s1[j], a, bb[j]);
        }

        // exp * invZ in registers, masked
        bool msk=(s0>=t0);
        float4 e[4];
        #pragma unroll
        for(int j=0;j<4;j++){
            int sg0=s0+j*8+2*tg, sg1=sg0+1;
            float4 S=s1[j];
            e[j].x=(!msk||qg0>=sg0)?__expf(S.x*0.125f)*izv[j][0]:0.f;
            e[j].y=(!msk||qg0>=sg1)?__expf(S.y*0.125f)*izv[j][1]:0.f;
            e[j].z=(!msk||qg1>=sg0)?__expf(S.z*0.125f)*izv[j][0]:0.f;
            e[j].w=(!msk||qg1>=sg1)?__expf(S.w*0.125f)*izv[j][1]:0.f;
        }
        // pack C-frags -> A-frags
        uint32_t aP[2][4];
        #pragma unroll
        for(int k2=0;k2<2;k2++){
            aP[k2][0]=h2u(e[2*k2].x,   e[2*k2].y);
            aP[k2][1]=h2u(e[2*k2].z,   e[2*k2].w);
            aP[k2][2]=h2u(e[2*k2+1].x, e[2*k2+1].y);
            aP[k2][3]=h2u(e[2*k2+1].z, e[2*k2+1].w);
        }

        // stage2: O[16q x 64d] += P(16x32).V(32x64)
        #pragma unroll
        for(int k2=0;k2<2;k2++){
            uint32_t bb[8][2];
            #pragma unroll
            for(int nt=0;nt<8;nt++) ldmBT(bb[nt], vToff + (k2*16*72 + nt*8)*2);
            #pragma unroll
            for(int nt=0;nt<8;nt++) mma16(oacc[nt], aP[k2], bb[nt]);
        }
    }

    __half* ob=g_att+((size_t)bh*T_+t0)*D_;
    int q0=w*16+g;
    #pragma unroll
    for(int nt=0;nt<8;nt++){
        int d=nt*8+2*tg;
        *(__half2*)(ob+(size_t)q0*D_+d)     = __floats2half2_rn(oacc[nt].x, oacc[nt].y);
        *(__half2*)(ob+(size_t)(q0+8)*D_+d) = __floats2half2_rn(oacc[nt].z, oacc[nt].w);
    }
}

// =====================================================================
// K4: output projection + bias (R15-passing, unchanged).
// =====================================================================
__global__ __launch_bounds__(256) void oproj_kernel(
    const float* __restrict__ bo, float* __restrict__ out)
{
    __shared__ __half As[2][128*40];
    __shared__ __half Bs[2][32*136];
    int tid=threadIdx.x, lane=tid&31, w=tid>>5;
    int g=lane>>2, tg=lane&3;
    int wm=w&1, wn=w>>1;
    int m0=blockIdx.x*128, n0=blockIdx.y*128;

    uint32_t asb[2]={(uint32_t)__cvta_generic_to_shared(As[0]),
                     (uint32_t)__cvta_generic_to_shared(As[1])};
    uint32_t bsb[2]={(uint32_t)__cvta_generic_to_shared(Bs[0]),
                     (uint32_t)__cvta_generic_to_shared(Bs[1])};

    float4 c[4][4];
    #pragma unroll
    for(int i=0;i<4;i++)
        #pragma unroll
        for(int j=0;j<4;j++) c[i][j]=make_float4(0.f,0.f,0.f,0.f);

    const int NC = C_/32;
    auto prefetch = [&](int ch, int p){
        int k0=ch*32, hk=k0>>6, dk=k0&32 ? 32 : 0;
        #pragma unroll
        for(int i=0;i<2;i++){
            int u=tid+i*256, r=u>>2, un=u&3;
            int mg=m0+r, b=mg>>11, t=mg&2047;
            cpa16(asb[p] + (r*40+un*8)*2,
                  g_att + (((size_t)(b*H_+hk))*T_+t)*D_ + dk + un*8);
        }
        #pragma unroll
        for(int i=0;i<2;i++){
            int u=tid+i*256, r=u>>4, un=u&15;
            cpa16(bsb[p] + (r*136+un*8)*2,
                  g_woh + (size_t)(k0+r)*C_ + n0 + un*8);
        }
        CP_COMMIT();
    };

    prefetch(0, 0);
    for(int ch=0; ch<NC; ch++){
        int p=ch&1;
        __syncthreads();
        if(ch+1<NC){ prefetch(ch+1, p^1); CP_WAIT1(); }
        else       { CP_WAIT0(); }
        __syncthreads();

        uint32_t aoff = asb[p] + (ROWA(lane)*40 + KOFA(lane))*2;
        uint32_t btof = bsb[p] + (ROWT(lane)*136)*2;
        #pragma unroll
        for(int ks=0;ks<2;ks++){
            uint32_t a[4][4], bb[4][2];
            #pragma unroll
            for(int i=0;i<4;i++) ldmA(a[i], aoff + ((wm*4+i)*16*40 + ks*16)*2);
            #pragma unroll
            for(int j=0;j<4;j++) ldmBT(bb[j], btof + (ks*16*136 + (wn*4+j)*8)*2);
            #pragma unroll
            for(int i=0;i<4;i++)
                #pragma unroll
                for(int j=0;j<4;j++) mma16(c[i][j], a[i], bb[j]);
        }
    }
    #pragma unroll
    for(int i=0;i<4;i++){
        int m=m0+wm*64+i*16+g;
        #pragma unroll
        for(int j=0;j<4;j++){
            int n=n0+wn*32+j*8+2*tg;
            float b0v=bo[n], b1v=bo[n+1];
            *(float2*)(out+(size_t)m*C_+n)     = make_float2(c[i][j].x+b0v, c[i][j].y+b1v);
            *(float2*)(out+(size_t)(m+8)*C_+n) = make_float2(c[i][j].z+b0v, c[i][j].w+b1v);
        }
    }
}

// =====================================================================
extern "C" void kernel_launch(void* const* d_in, const int* in_sizes, int n_in,
                              void* d_out, int out_size)
{
    const float* x  = (const float*)d_in[0];
    const float* Wq = (const float*)d_in[1];
    const float* Wk = (const float*)d_in[2];
    const float* Wv = (const float*)d_in[3];
    const float* Wo = (const float*)d_in[4];
    const float* bo = (const float*)d_in[5];
    float* out = (float*)d_out;

    cvt_all_kernel<<<6144, 256>>>(x, Wq, Wk, Wv, Wo);

    qkv_kernel   <<<dim3(T_/128, BH_), 256>>>();
    colsum_kernel<<<dim3(T_/128, BH_), 256>>>();
    attn_kernel  <<<dim3(T_/128, BH_), 256>>>();
    oproj_kernel <<<dim3((B_*T_)/128, C_/128), 256>>>(bo, out);
}